// round 3
// baseline (speedup 1.0000x reference)
#include <cuda_runtime.h>
#include <cstdint>

// QuantumLSTM: B=2048, T=64, IN=8, HID=6 qubits, OUT=8, NLAYERS=2.
//
// X-basis formulation: H RX(t) H = RZ(t); (HxH) CNOT(c,t) (HxH) = CNOT(t,c).
// In this frame the state is pure-phase throughout the circuit:
//   psi'_k = (1/8) e^{i beta_k}
// and since both RZ layers are phase-adds and the CNOT ring is the SAME
// permutation sigma for every gate circuit,
//   beta^{(g)}_k = a_{sigma^2(k)} + C^{(g)}_k,
//   C^{(g)}_k    = A1^{(g)}_{sigma^2(k)} + A2^{(g)}_{sigma(k)}   (precomputed).
// One warp per sample; lane l holds indices k=l (lo) and k=l+32 (hi);
// wire w <-> bit (5-w) of k.

namespace {
constexpr int BATCH = 2048;
constexpr int TSTEPS = 64;
constexpr int NIN = 8;
constexpr int NOUT = 8;
constexpr int WARPS_PER_BLOCK = 8;
constexpr float TWO_PI = 6.28318530717958647692f;
}

__device__ __forceinline__ float shx(float v, int m) {
    return __shfl_xor_sync(0xffffffffu, v, m);
}
__device__ __forceinline__ float shi(float v, int src) {
    return __shfl_sync(0xffffffffu, v, src);
}
__device__ __forceinline__ float sigmoidf_(float x) {
    return 1.0f / (1.0f + __expf(-x));
}
__device__ __forceinline__ float tanhf_(float x) {
    return 1.0f - 2.0f / (__expf(2.0f * x) + 1.0f);
}
__device__ __forceinline__ float reduce2pi(float a) {
    return a - TWO_PI * rintf(a * (1.0f / TWO_PI));
}

// X-basis CNOT ring (orig pairs (w,w+1) -> ctrl/tgt swapped), composed
// permutation source: state'[k] = state[sigma(k)]. Gates applied in time
// order G1..G6; innermost map applied to k is G6 (the last gate).
__device__ __forceinline__ int ring_src_x(int k) {
    int j = k;
    j ^= (j >> 5) & 1;         // G6: ctrl wire0(bit5) -> tgt wire5(bit0)
    j ^= (j & 1) << 1;         // G5: ctrl bit0 -> tgt bit1
    j ^= ((j >> 1) & 1) << 2;  // G4
    j ^= ((j >> 2) & 1) << 3;  // G3
    j ^= ((j >> 3) & 1) << 4;  // G2
    j ^= ((j >> 4) & 1) << 5;  // G1: ctrl bit4 -> tgt bit5
    return j;
}

// A_layer(j) = sum_w (+-0.5) * w6[w], sign + iff bit (5-w) of j set.
__device__ __forceinline__ float phaseA(const float* w6, int j) {
    float s = 0.0f;
#pragma unroll
    for (int w = 0; w < 6; w++)
        s += (((j >> (5 - w)) & 1) ? 0.5f : -0.5f) * w6[w];
    return s;
}

__global__ void __launch_bounds__(32 * WARPS_PER_BLOCK, 2) qlstm_kernel(
    const float* __restrict__ x,      // [B, T, NIN]
    const float* __restrict__ W_in,   // [6, 16]
    const float* __restrict__ b_in,   // [6]
    const float* __restrict__ W_out,  // [8, 6]
    const float* __restrict__ b_out,  // [8]
    const float* __restrict__ wf,     // [2, 6]
    const float* __restrict__ wi,
    const float* __restrict__ wg,
    const float* __restrict__ wo,
    float* __restrict__ out)          // [B, T, NOUT]
{
    const int lane = threadIdx.x & 31;
    const int s = blockIdx.x * WARPS_PER_BLOCK + (threadIdx.x >> 5);

    // ---- composed permutation sigma, sigma^2 for this lane's slots ----
    const int s1Lo = ring_src_x(lane);
    const int s1Hi = ring_src_x(lane + 32);
    const int s2Lo = ring_src_x(s1Lo);
    const int s2Hi = ring_src_x(s1Hi);
    const int pLaneLo = s2Lo & 31;
    const int pLaneHi = s2Hi & 31;
    const float pHiLo = (s2Lo >> 5) ? 1.0f : 0.0f;
    const float pHiHi = (s2Hi >> 5) ? 1.0f : 0.0f;

    // ---- per-gate phase constants C (range-reduced) ----
    float CLo[4], CHi[4];
    {
        const float* wp[4] = {wf, wi, wg, wo};
#pragma unroll
        for (int g = 0; g < 4; g++) {
            CLo[g] = reduce2pi(phaseA(wp[g], s2Lo) + phaseA(wp[g] + 6, s1Lo));
            CHi[g] = reduce2pi(phaseA(wp[g], s2Hi) + phaseA(wp[g] + 6, s1Hi));
        }
    }

    // ---- embedding sign per wire (lo slot k=lane; bit5=0 -> wire0 = -0.5) ----
    float sgn[6];
#pragma unroll
    for (int w = 0; w < 6; w++)
        sgn[w] = ((lane >> (5 - w)) & 1) ? 0.5f : -0.5f;

    // ---- G[ch][k] = (1/4096) sum_w W_out[ch][w] (1 - 2 b_w(k)) ----
    float Glo[8], Ghi[8];
#pragma unroll
    for (int ch = 0; ch < 8; ch++) {
        float glo = 0.0f, ghi = 0.0f;
#pragma unroll
        for (int w = 0; w < 6; w++) {
            float wv = W_out[ch * 6 + w];
            float zlo = ((lane >> (5 - w)) & 1) ? -wv : wv;
            float zhi = (w == 0) ? -wv : zlo;   // hi slot flips only wire0
            glo += zlo;
            ghi += zhi;
        }
        Glo[ch] = glo * (1.0f / 4096.0f);
        Ghi[ch] = ghi * (1.0f / 4096.0f);
    }
    const float boutv = b_out[lane & 7];

    // ---- hoisted W_in row (lane w<6 computes angle y_w) ----
    float winrow[16];
    float binv = 0.0f;
#pragma unroll
    for (int j = 0; j < 16; j++) winrow[j] = 0.0f;
    if (lane < 6) {
#pragma unroll
        for (int j = 0; j < 16; j++) winrow[j] = W_in[lane * 16 + j];
        binv = b_in[lane];
    }

    // butterfly signs
    const float sg16 = (lane & 16) ? -1.0f : 1.0f;
    const float sg8  = (lane & 8)  ? -1.0f : 1.0f;
    const float sg4  = (lane & 4)  ? -1.0f : 1.0f;
    const float sg2  = (lane & 2)  ? -1.0f : 1.0f;
    const float sg1  = (lane & 1)  ? -1.0f : 1.0f;

    const float* xrow = x + (size_t)s * TSTEPS * NIN;
    float* orow = out + (size_t)s * TSTEPS * NOUT;

    float creg = 0.0f, hreg = 0.0f;  // every lane owns channel (lane&7), x4 replicated

    for (int t = 0; t < TSTEPS; t++) {
        // ---- y = W_in [h; x] + b  (meaningful on lanes 0..5) ----
        float xv = 0.0f;
        if (lane < NIN) xv = xrow[t * NIN + lane];
        float y = binv;
#pragma unroll
        for (int j = 0; j < 8; j++) y = fmaf(winrow[j], shi(hreg, j), y);
#pragma unroll
        for (int j = 0; j < 8; j++) y = fmaf(winrow[8 + j], shi(xv, j), y);

        float yb[6];
#pragma unroll
        for (int w = 0; w < 6; w++) yb[w] = shi(y, w);

        // ---- embedding phase a_k (lo slot), permuted gather a_{sigma^2(k)} ----
        float aLo = 0.0f;
#pragma unroll
        for (int w = 0; w < 6; w++) aLo = fmaf(sgn[w], yb[w], aLo);
        // a at any index j = aLo(lane j&31) + bit5(j)*y0
        float apermLo = fmaf(pHiLo, yb[0], shi(aLo, pLaneLo));
        float apermHi = fmaf(pHiHi, yb[0], shi(aLo, pLaneHi));

        // ---- final phases + amplitudes for all 4 gate circuits ----
        float lr[4], li[4], hr[4], hi[4];
#pragma unroll
        for (int g = 0; g < 4; g++) {
            float bl = reduce2pi(apermLo + CLo[g]);
            float bh = reduce2pi(apermHi + CHi[g]);
            __sincosf(bl, &li[g], &lr[g]);
            __sincosf(bh, &hi[g], &hr[g]);
        }

        // ---- inverse H^x6: 5 cross-lane butterfly stages (unnormalized) ----
#pragma unroll
        for (int st = 0; st < 5; st++) {
            const int m = 16 >> st;
            const float sg = (st == 0) ? sg16 : (st == 1) ? sg8 :
                             (st == 2) ? sg4  : (st == 3) ? sg2 : sg1;
#pragma unroll
            for (int g = 0; g < 4; g++) {
                float p;
                p = shx(lr[g], m); lr[g] = fmaf(sg, lr[g], p);
                p = shx(li[g], m); li[g] = fmaf(sg, li[g], p);
                p = shx(hr[g], m); hr[g] = fmaf(sg, hr[g], p);
                p = shx(hi[g], m); hi[g] = fmaf(sg, hi[g], p);
            }
        }

        // ---- slot butterfly (wire 0) + probs ----
        float plo[4], phi[4];
#pragma unroll
        for (int g = 0; g < 4; g++) {
            float ar = lr[g] + hr[g], br = lr[g] - hr[g];
            float ai = li[g] + hi[g], bi = li[g] - hi[g];
            plo[g] = fmaf(ar, ar, ai * ai);
            phi[g] = fmaf(br, br, bi * bi);
        }

        // ---- per-lane partials for all (gate, channel), fused 32-wide reduce ----
        float q[32];
#pragma unroll
        for (int g = 0; g < 4; g++)
#pragma unroll
            for (int ch = 0; ch < 8; ch++)
                q[g * 8 + ch] = fmaf(plo[g], Glo[ch], phi[g] * Ghi[ch]);

#pragma unroll
        for (int half = 16; half >= 1; half >>= 1) {
            const bool upper = (lane & half) != 0;
#pragma unroll
            for (int i = 0; i < 16; i++) {
                if (i < half) {
                    float keep = upper ? q[i + half] : q[i];
                    float send = upper ? q[i] : q[i + half];
                    q[i] = keep + shx(send, half);
                }
            }
        }
        // lane l now holds S = z-partial for (gate = l>>3, ch = l&7)
        const float S = q[0];
        const int ch = lane & 7;
        float zf = shi(S, ch)      + boutv;
        float zi = shi(S, ch + 8)  + boutv;
        float zg = shi(S, ch + 16) + boutv;
        float zo = shi(S, ch + 24) + boutv;

        // ---- LSTM cell (lane owns channel ch, x4 replicated) ----
        float fg = sigmoidf_(zf);
        float ig = sigmoidf_(zi);
        float gg = tanhf_(zg);
        float og = sigmoidf_(zo);
        creg = fmaf(fg, creg, ig * gg);
        hreg = og * tanhf_(creg);
        if (lane < NOUT) orow[t * NOUT + lane] = hreg;
    }
}

extern "C" void kernel_launch(void* const* d_in, const int* in_sizes, int n_in,
                              void* d_out, int out_size) {
    const float* x     = (const float*)d_in[0];
    const float* W_in  = (const float*)d_in[1];
    const float* b_in  = (const float*)d_in[2];
    const float* W_out = (const float*)d_in[3];
    const float* b_out = (const float*)d_in[4];
    const float* wf    = (const float*)d_in[5];
    const float* wi    = (const float*)d_in[6];
    const float* wg    = (const float*)d_in[7];
    const float* wo    = (const float*)d_in[8];
    float* out = (float*)d_out;

    qlstm_kernel<<<BATCH / WARPS_PER_BLOCK, 32 * WARPS_PER_BLOCK>>>(
        x, W_in, b_in, W_out, b_out, wf, wi, wg, wo, out);
}

// round 4
// speedup vs baseline: 1.0415x; 1.0415x over previous
#include <cuda_runtime.h>
#include <cstdint>

// QuantumLSTM: B=2048, T=64, IN=8, HID=6 qubits, OUT=8, NLAYERS=2.
//
// X-basis formulation: H RX H = RZ; (HxH) CNOT(c,t) (HxH) = CNOT(t,c).
// State stays pure-phase: psi_k = (1/8) e^{i beta_k}, with
//   beta^{(g)}_k = a_{sigma^2(k)} + C^{(g)}_k   (sigma = composed CNOT ring).
// Measurement WITHOUT leaving the X basis:  H Z_w H = X_w, so
//   <Z_w> = <phi| X_w |phi> = (1/64) sum_k cos(beta_{k xor e_w} - beta_k).
// The diff splits into a gate-independent part Da (from shuffles of aperm)
// plus per-lane constants dC = C(k xor e_w) - C(k), precomputed per gate.
// One warp per sample; lane l holds k=l (lo) and k=l+32 (hi); wire w <-> bit (5-w).

namespace {
constexpr int BATCH = 2048;
constexpr int TSTEPS = 64;
constexpr float TWO_PI = 6.28318530717958647692f;
}

__device__ __forceinline__ float shx(float v, int m) {
    return __shfl_xor_sync(0xffffffffu, v, m);
}
__device__ __forceinline__ float shi(float v, int src) {
    return __shfl_sync(0xffffffffu, v, src);
}
__device__ __forceinline__ float sigmoidf_(float x) {
    return 1.0f / (1.0f + __expf(-x));
}
__device__ __forceinline__ float tanhf_(float x) {
    return 1.0f - 2.0f / (__expf(2.0f * x) + 1.0f);
}
__device__ __forceinline__ float reduce2pi(float a) {
    return a - TWO_PI * rintf(a * (1.0f / TWO_PI));
}

// X-basis CNOT ring (orig pairs (w,w+1) -> ctrl/tgt swapped), composed
// permutation source: state'[k] = state[sigma(k)].
__device__ __forceinline__ int ring_src_x(int k) {
    int j = k;
    j ^= (j >> 5) & 1;         // G6: ctrl wire0(bit5) -> tgt wire5(bit0)
    j ^= (j & 1) << 1;         // G5
    j ^= ((j >> 1) & 1) << 2;  // G4
    j ^= ((j >> 2) & 1) << 3;  // G3
    j ^= ((j >> 3) & 1) << 4;  // G2
    j ^= ((j >> 4) & 1) << 5;  // G1
    return j;
}

// A_layer(j) = sum_w (+-0.5) * w6[w], sign + iff bit (5-w) of j set.
__device__ __forceinline__ float phaseA(const float* w6, int j) {
    float s = 0.0f;
#pragma unroll
    for (int w = 0; w < 6; w++)
        s += (((j >> (5 - w)) & 1) ? 0.5f : -0.5f) * w6[w];
    return s;
}

// C^{(g)}(j) = A1(sigma^2 j) + A2(sigma j)
__device__ __forceinline__ float Cphase(const float* wp, int j) {
    int s1 = ring_src_x(j);
    return phaseA(wp, ring_src_x(s1)) + phaseA(wp + 6, s1);
}

__global__ void __launch_bounds__(32, 14) qlstm_kernel(
    const float* __restrict__ x,      // [B, T, 8]
    const float* __restrict__ W_in,   // [6, 16]
    const float* __restrict__ b_in,   // [6]
    const float* __restrict__ W_out,  // [8, 6]
    const float* __restrict__ b_out,  // [8]
    const float* __restrict__ wf,     // [2, 6]
    const float* __restrict__ wi,
    const float* __restrict__ wg,
    const float* __restrict__ wo,
    float* __restrict__ out)          // [B, T, 8]
{
    const int lane = threadIdx.x;
    const int s = blockIdx.x;

    const int kLo = lane;
    const int kHi = lane + 32;

    // ---- per-lane sign tables for aperm = a(sigma^2(k)) ----
    const int s2Lo = ring_src_x(ring_src_x(kLo));
    const int s2Hi = ring_src_x(ring_src_x(kHi));
    float sgnP[6], sgnH[6];
#pragma unroll
    for (int w = 0; w < 6; w++) {
        sgnP[w] = ((s2Lo >> (5 - w)) & 1) ? 0.5f : -0.5f;
        sgnH[w] = ((s2Hi >> (5 - w)) & 1) ? 0.5f : -0.5f;
    }

    // ---- per-gate constant phase diffs dC (range-reduced) ----
    float dc0[4], dcL[4][5], dcH[4][5];
    {
        const float* wp[4] = {wf, wi, wg, wo};
#pragma unroll
        for (int g = 0; g < 4; g++) {
            float cLo = Cphase(wp[g], kLo);
            float cHi = Cphase(wp[g], kHi);
            dc0[g] = reduce2pi(cHi - cLo);
#pragma unroll
            for (int i = 0; i < 5; i++) {
                int m = 16 >> i;  // wire w = i+1 <-> bit (5-w)
                dcL[g][i] = reduce2pi(Cphase(wp[g], kLo ^ m) - cLo);
                dcH[g][i] = reduce2pi(Cphase(wp[g], kHi ^ m) - cHi);
            }
        }
    }

    // ---- W_out row for my channel (scaled; wire0 carries x2 for the
    //      slot-pair double count) ----
    const int ch = lane & 7;
    float woutS[6];
#pragma unroll
    for (int w = 0; w < 6; w++)
        woutS[w] = W_out[ch * 6 + w] * ((w == 0) ? (2.0f / 64.0f) : (1.0f / 64.0f));
    const float boutv = b_out[ch];

    // ---- hoisted W_in row (lane w<6 computes angle y_w) ----
    float winrow[16];
    float binv = 0.0f;
#pragma unroll
    for (int j = 0; j < 16; j++) winrow[j] = 0.0f;
    if (lane < 6) {
#pragma unroll
        for (int j = 0; j < 16; j++) winrow[j] = W_in[lane * 16 + j];
        binv = b_in[lane];
    }

    const float* xrow = x + (size_t)s * TSTEPS * 8;
    float* orow = out + (size_t)s * TSTEPS * 8;

    float creg = 0.0f, hreg = 0.0f;  // every lane owns channel (lane&7), x4 replicated

    for (int t = 0; t < TSTEPS; t++) {
        // ---- y = W_in [h; x] + b  (meaningful on lanes 0..5) ----
        float xv = 0.0f;
        if (lane < 8) xv = xrow[t * 8 + lane];
        float y = binv;
#pragma unroll
        for (int j = 0; j < 8; j++) y = fmaf(winrow[j], shi(hreg, j), y);
#pragma unroll
        for (int j = 0; j < 8; j++) y = fmaf(winrow[8 + j], shi(xv, j), y);

        float yb[6];
#pragma unroll
        for (int w = 0; w < 6; w++) yb[w] = shi(y, w);

        // ---- aperm phases (per-lane, no shuffles) ----
        float apl = 0.0f, aph = 0.0f;
#pragma unroll
        for (int w = 0; w < 6; w++) {
            apl = fmaf(sgnP[w], yb[w], apl);
            aph = fmaf(sgnH[w], yb[w], aph);
        }

        // ---- gate-independent phase diffs ----
        float Da0 = reduce2pi(aph - apl);
        float DaL[5], DaH[5];
#pragma unroll
        for (int i = 0; i < 5; i++) {
            const int m = 16 >> i;
            DaL[i] = reduce2pi(shx(apl, m) - apl);
            DaH[i] = reduce2pi(shx(aph, m) - aph);
        }

        // ---- per-lane expval partials q[g*6+w] ----
        float q[24];
#pragma unroll
        for (int g = 0; g < 4; g++) {
            q[g * 6] = __cosf(Da0 + dc0[g]);
#pragma unroll
            for (int i = 0; i < 5; i++)
                q[g * 6 + 1 + i] = __cosf(DaL[i] + dcL[g][i])
                                 + __cosf(DaH[i] + dcH[g][i]);
        }

        // ---- 24-wide transpose-reduce (pad 24..31 with zeros) ----
        {
            const bool up = (lane & 16) != 0;
#pragma unroll
            for (int i = 0; i < 16; i++) {
                float hi_e = (i < 8) ? q[i + 16] : 0.0f;
                float keep = up ? hi_e : q[i];
                float send = up ? q[i] : hi_e;
                q[i] = keep + shx(send, 16);
            }
        }
#pragma unroll
        for (int half = 8; half >= 1; half >>= 1) {
            const bool up = (lane & half) != 0;
#pragma unroll
            for (int i = 0; i < half; i++) {
                float keep = up ? q[i + half] : q[i];
                float send = up ? q[i] : q[i + half];
                q[i] = keep + shx(send, half);
            }
        }
        // lane l<24 now holds e[g=l/6][w=l%6]; lanes 24..31 hold 0.
        const float S = q[0];

        // ---- shuffle-matmul: lane (g=lane>>3, ch=lane&7) computes z ----
        const int base = (lane >> 3) * 6;
        float z = boutv;
#pragma unroll
        for (int w = 0; w < 6; w++) z = fmaf(woutS[w], shi(S, base + w), z);

        // gather the 4 gate values for my channel
        float zf = shi(z, ch);
        float zi = shi(z, ch + 8);
        float zg = shi(z, ch + 16);
        float zo = shi(z, ch + 24);

        // ---- LSTM cell ----
        float fg = sigmoidf_(zf);
        float ig = sigmoidf_(zi);
        float gg = tanhf_(zg);
        float og = sigmoidf_(zo);
        creg = fmaf(fg, creg, ig * gg);
        hreg = og * tanhf_(creg);
        if (lane < 8) orow[t * 8 + lane] = hreg;
    }
}

extern "C" void kernel_launch(void* const* d_in, const int* in_sizes, int n_in,
                              void* d_out, int out_size) {
    const float* x     = (const float*)d_in[0];
    const float* W_in  = (const float*)d_in[1];
    const float* b_in  = (const float*)d_in[2];
    const float* W_out = (const float*)d_in[3];
    const float* b_out = (const float*)d_in[4];
    const float* wf    = (const float*)d_in[5];
    const float* wi    = (const float*)d_in[6];
    const float* wg    = (const float*)d_in[7];
    const float* wo    = (const float*)d_in[8];
    float* out = (float*)d_out;

    qlstm_kernel<<<BATCH, 32>>>(x, W_in, b_in, W_out, b_out, wf, wi, wg, wo, out);
}

// round 7
// speedup vs baseline: 1.4123x; 1.3560x over previous
#include <cuda_runtime.h>
#include <cstdint>

// QuantumLSTM: B=2048, T=64, IN=8, HID=6 qubits, OUT=8, NLAYERS=2.
//
// X-basis: H RX H = RZ; (HxH) CNOT(c,t) (HxH) = CNOT(t,c). State stays
// pure-phase: beta^{(g)}_k = a_{sigma^2(k)} + C^{(g)}_k. Expvals in-basis:
// <Z_w> = (1/64) sum_k cos(beta_{k xor e_w} - beta_k); the diff splits into
// data part Da (shuffles of aperm) + per-lane constants dC.
// This round: folded W_in (no explicit y), gate-permuted selection-free
// reduce stages, float4 x loads, warp-parallel activations via MUFU.TANH,
// split h/x accumulation chains.

namespace {
constexpr int BATCH = 2048;
constexpr int TSTEPS = 64;
constexpr float TWO_PI = 6.28318530717958647692f;
}

__device__ __forceinline__ float shx(float v, int m) {
    return __shfl_xor_sync(0xffffffffu, v, m);
}
__device__ __forceinline__ float shi(float v, int src) {
    return __shfl_sync(0xffffffffu, v, src);
}
__device__ __forceinline__ float tanh_fast(float x) {
    float r;
    asm("tanh.approx.f32 %0, %1;" : "=f"(r) : "f"(x));
    return r;
}
__device__ __forceinline__ float reduce2pi(float a) {
    return a - TWO_PI * rintf(a * (1.0f / TWO_PI));
}

// X-basis CNOT ring composed permutation: state'[k] = state[sigma(k)].
__device__ __forceinline__ int ring_src_x(int k) {
    int j = k;
    j ^= (j >> 5) & 1;
    j ^= (j & 1) << 1;
    j ^= ((j >> 1) & 1) << 2;
    j ^= ((j >> 2) & 1) << 3;
    j ^= ((j >> 3) & 1) << 4;
    j ^= ((j >> 4) & 1) << 5;
    return j;
}

__device__ __forceinline__ float phaseA(const float* w6, int j) {
    float s = 0.0f;
#pragma unroll
    for (int w = 0; w < 6; w++)
        s += (((j >> (5 - w)) & 1) ? 0.5f : -0.5f) * w6[w];
    return s;
}

// C^{(g)}(j) = A1(sigma^2 j) + A2(sigma j)
__device__ __forceinline__ float Cphase(const float* wp, int j) {
    int s1 = ring_src_x(j);
    return phaseA(wp, ring_src_x(s1)) + phaseA(wp + 6, s1);
}

__global__ void __launch_bounds__(32, 14) qlstm_kernel(
    const float* __restrict__ x,      // [B, T, 8]
    const float* __restrict__ W_in,   // [6, 16]
    const float* __restrict__ b_in,   // [6]
    const float* __restrict__ W_out,  // [8, 6]
    const float* __restrict__ b_out,  // [8]
    const float* __restrict__ wf,     // [2, 6]
    const float* __restrict__ wi,
    const float* __restrict__ wg,
    const float* __restrict__ wo,
    float* __restrict__ out)          // [B, T, 8]
{
    const int lane = threadIdx.x;
    const int s = blockIdx.x;

    const int kLo = lane;
    const int kHi = lane + 32;
    const int lg = (lane >> 3) & 3;   // lane's gate-group bits
    const int ch = lane & 7;          // lane's LSTM channel

    // ---- embedding sign vectors for aperm = a(sigma^2(k)) ----
    const int s2Lo = ring_src_x(ring_src_x(kLo));
    const int s2Hi = ring_src_x(ring_src_x(kHi));
    float sgnP[6], sgnH[6];
#pragma unroll
    for (int w = 0; w < 6; w++) {
        sgnP[w] = ((s2Lo >> (5 - w)) & 1) ? 0.5f : -0.5f;
        sgnH[w] = ((s2Hi >> (5 - w)) & 1) ? 0.5f : -0.5f;
    }

    // ---- fold sign vectors through W_in: apl = WP.[h;x] + bP ----
    float WP[16], WH[16];
    float bP = 0.0f, bH = 0.0f;
#pragma unroll
    for (int j = 0; j < 16; j++) { WP[j] = 0.0f; WH[j] = 0.0f; }
#pragma unroll
    for (int w = 0; w < 6; w++) {
        float bw = b_in[w];
        bP = fmaf(sgnP[w], bw, bP);
        bH = fmaf(sgnH[w], bw, bH);
#pragma unroll
        for (int j = 0; j < 16; j++) {
            float wv = W_in[w * 16 + j];
            WP[j] = fmaf(sgnP[w], wv, WP[j]);
            WH[j] = fmaf(sgnH[w], wv, WH[j]);
        }
    }

    // ---- per-gate constant phase diffs, PRE-PERMUTED by lane's gate bits ----
    // slot jg holds constants for gate g = jg ^ lg
    float dc0P[4], dcLP[4][5], dcHP[4][5];
#pragma unroll
    for (int jg = 0; jg < 4; jg++) {
        int g = jg ^ lg;
        const float* wp = (g == 0) ? wf : (g == 1) ? wi : (g == 2) ? wg : wo;
        float cLo = Cphase(wp, kLo);
        float cHi = Cphase(wp, kHi);
        dc0P[jg] = reduce2pi(cHi - cLo);
#pragma unroll
        for (int i = 0; i < 5; i++) {
            int m = 16 >> i;  // wire w=i+1 <-> bit (4-i)
            dcLP[jg][i] = reduce2pi(Cphase(wp, kLo ^ m) - cLo);
            dcHP[jg][i] = reduce2pi(Cphase(wp, kHi ^ m) - cHi);
        }
    }

    // ---- W_out row (wire0 scaled x2 for the slot-pair double count) ----
    float woutS[6];
#pragma unroll
    for (int w = 0; w < 6; w++)
        woutS[w] = W_out[ch * 6 + w] * ((w == 0) ? (2.0f / 64.0f) : (1.0f / 64.0f));
    const float boutv = b_out[ch];

    // ---- branch-free activation via tanh:
    //   sigmoid(z) = 0.5 + 0.5 tanh(z/2);  tanh(z) = tanh(z).
    //   act = aT * tanh(sT * z) + bT
    const float sT = (lg == 2) ? 1.0f : 0.5f;
    const float aT = (lg == 2) ? 1.0f : 0.5f;
    const float bT = (lg == 2) ? 0.0f : 0.5f;

    const float4* xrow = (const float4*)(x + (size_t)s * TSTEPS * 8);
    float* orow = out + (size_t)s * TSTEPS * 8;

    float creg = 0.0f, hreg = 0.0f;  // lane owns channel ch (x4 replicated)

    for (int t = 0; t < TSTEPS; t++) {
        // ---- x_t via two float4 broadcast loads; x-chain independent of h ----
        float4 xa = xrow[t * 2];
        float4 xb = xrow[t * 2 + 1];
        float xpl = bP, xph = bH;
        {
            float xs[8] = {xa.x, xa.y, xa.z, xa.w, xb.x, xb.y, xb.z, xb.w};
#pragma unroll
            for (int j = 0; j < 8; j++) {
                xpl = fmaf(WP[8 + j], xs[j], xpl);
                xph = fmaf(WH[8 + j], xs[j], xph);
            }
        }

        // ---- h-chain (recurrence-critical), joined with x-chain ----
        float hpl = 0.0f, hph = 0.0f;
#pragma unroll
        for (int j = 0; j < 8; j++) {
            float hj = shi(hreg, j);
            hpl = fmaf(WP[j], hj, hpl);
            hph = fmaf(WH[j], hj, hph);
        }
        float apl = reduce2pi(xpl + hpl);
        float aph = reduce2pi(xph + hph);

        // ---- gate-independent phase diffs (|.| <= 2pi) ----
        float Da0 = aph - apl;
        float DaL[5], DaH[5];
#pragma unroll
        for (int i = 0; i < 5; i++) {
            const int m = 16 >> i;
            DaL[i] = shx(apl, m) - apl;
            DaH[i] = shx(aph, m) - aph;
        }

        // ---- per-lane partials, gate-permuted slots: q[jg*8 + jw] ----
        float q[32];
#pragma unroll
        for (int jg = 0; jg < 4; jg++) {
            q[jg * 8] = __cosf(Da0 + dc0P[jg]);
#pragma unroll
            for (int i = 0; i < 5; i++)
                q[jg * 8 + 1 + i] = __cosf(DaL[i] + dcLP[jg][i])
                                  + __cosf(DaH[i] + dcHP[jg][i]);
            q[jg * 8 + 6] = 0.0f;
            q[jg * 8 + 7] = 0.0f;
        }

        // ---- reduce: gate stages are SELECTION-FREE (xor-permuted) ----
#pragma unroll
        for (int i = 0; i < 16; i++)
            q[i] += shx(q[i + 16], 16);
#pragma unroll
        for (int i = 0; i < 8; i++)
            q[i] += shx(q[i + 8], 8);
        // w-stages (routed, with selects): masks 4, 2, 1 over 8 values
#pragma unroll
        for (int half = 4; half >= 1; half >>= 1) {
            const bool up = (lane & half) != 0;
#pragma unroll
            for (int i = 0; i < half; i++) {
                float keep = up ? q[i + half] : q[i];
                float send = up ? q[i] : q[i + half];
                q[i] = keep + shx(send, half);
            }
        }
        // lane l holds S for (gate = l>>3, w = l&7); w=6,7 are zero pads.
        const float S = q[0];

        // ---- z for (gate = l>>3, ch = l&7) via shuffle-matmul ----
        const int base = lane & 24;
        float z = boutv;
#pragma unroll
        for (int w = 0; w < 6; w++) z = fmaf(woutS[w], shi(S, base + w), z);

        // ---- activation FIRST (one MUFU.TANH per lane), then gather ----
        float act = fmaf(aT, tanh_fast(sT * z), bT);
        float fg = shi(act, ch);
        float ig = shi(act, ch + 8);
        float gg = shi(act, ch + 16);
        float og = shi(act, ch + 24);

        // ---- LSTM cell ----
        creg = fmaf(fg, creg, ig * gg);
        hreg = og * tanh_fast(creg);
        if (lane < 8) orow[t * 8 + lane] = hreg;
    }
}

extern "C" void kernel_launch(void* const* d_in, const int* in_sizes, int n_in,
                              void* d_out, int out_size) {
    const float* x     = (const float*)d_in[0];
    const float* W_in  = (const float*)d_in[1];
    const float* b_in  = (const float*)d_in[2];
    const float* W_out = (const float*)d_in[3];
    const float* b_out = (const float*)d_in[4];
    const float* wf    = (const float*)d_in[5];
    const float* wi    = (const float*)d_in[6];
    const float* wg    = (const float*)d_in[7];
    const float* wo    = (const float*)d_in[8];
    float* out = (float*)d_out;

    qlstm_kernel<<<BATCH, 32>>>(x, W_in, b_in, W_out, b_out, wf, wi, wg, wo, out);
}

// round 9
// speedup vs baseline: 1.9760x; 1.3991x over previous
#include <cuda_runtime.h>
#include <cstdint>

// QuantumLSTM: B=2048, T=64, IN=8, HID=6 qubits, OUT=8, NLAYERS=2.
//
// X-basis: H RX H = RZ; (HxH) CNOT(c,t) (HxH) = CNOT(t,c). State stays
// pure-phase: beta^{(g)}_k = a_{sigma^2(k)} + C^{(g)}_k. Expvals in-basis:
// <Z_w> = (1/64) sum_k cos(beta_{k xor e_w} - beta_k).
// Pair-dedup: each unordered pair's cosine computed ONCE per warp (weight 2):
// lane with (l&m)==0 handles its lo-slot pair, (l&m)==1 its hi-slot pair;
// one shfl_xor serves both orientations by sending the opposite slot.
// Dense 24-slot xor-permuted reduce (zero pads only in the routed w-stages).

namespace {
constexpr int BATCH = 2048;
constexpr int TSTEPS = 64;
constexpr float TWO_PI = 6.28318530717958647692f;
}

__device__ __forceinline__ float shx(float v, int m) {
    return __shfl_xor_sync(0xffffffffu, v, m);
}
__device__ __forceinline__ float shi(float v, int src) {
    return __shfl_sync(0xffffffffu, v, src);
}
__device__ __forceinline__ float tanh_fast(float x) {
    float r;
    asm("tanh.approx.f32 %0, %1;" : "=f"(r) : "f"(x));
    return r;
}
__device__ __forceinline__ float reduce2pi(float a) {
    return a - TWO_PI * rintf(a * (1.0f / TWO_PI));
}

// X-basis CNOT ring composed permutation: state'[k] = state[sigma(k)].
__device__ __forceinline__ int ring_src_x(int k) {
    int j = k;
    j ^= (j >> 5) & 1;
    j ^= (j & 1) << 1;
    j ^= ((j >> 1) & 1) << 2;
    j ^= ((j >> 2) & 1) << 3;
    j ^= ((j >> 3) & 1) << 4;
    j ^= ((j >> 4) & 1) << 5;
    return j;
}

__device__ __forceinline__ float phaseA(const float* w6, int j) {
    float s = 0.0f;
#pragma unroll
    for (int w = 0; w < 6; w++)
        s += (((j >> (5 - w)) & 1) ? 0.5f : -0.5f) * w6[w];
    return s;
}

// C^{(g)}(j) = A1(sigma^2 j) + A2(sigma j)
__device__ __forceinline__ float Cphase(const float* wp, int j) {
    int s1 = ring_src_x(j);
    return phaseA(wp, ring_src_x(s1)) + phaseA(wp + 6, s1);
}

__global__ void __launch_bounds__(32, 14) qlstm_kernel(
    const float* __restrict__ x,      // [B, T, 8]
    const float* __restrict__ W_in,   // [6, 16]
    const float* __restrict__ b_in,   // [6]
    const float* __restrict__ W_out,  // [8, 6]
    const float* __restrict__ b_out,  // [8]
    const float* __restrict__ wf,     // [2, 6]
    const float* __restrict__ wi,
    const float* __restrict__ wg,
    const float* __restrict__ wo,
    float* __restrict__ out)          // [B, T, 8]
{
    const int lane = threadIdx.x;
    const int s = blockIdx.x;

    const int kLo = lane;
    const int kHi = lane + 32;
    const int lg = (lane >> 3) & 3;   // lane's gate-group bits
    const int ch = lane & 7;          // lane's LSTM channel

    // ---- embedding sign vectors for aperm = a(sigma^2(k)) ----
    const int s2Lo = ring_src_x(ring_src_x(kLo));
    const int s2Hi = ring_src_x(ring_src_x(kHi));
    float sgnP[6], sgnH[6];
#pragma unroll
    for (int w = 0; w < 6; w++) {
        sgnP[w] = ((s2Lo >> (5 - w)) & 1) ? 0.5f : -0.5f;
        sgnH[w] = ((s2Hi >> (5 - w)) & 1) ? 0.5f : -0.5f;
    }

    // ---- fold sign vectors through W_in: apl = WP.[h;x] + bP ----
    float WP[16], WH[16];
    float bP = 0.0f, bH = 0.0f;
#pragma unroll
    for (int j = 0; j < 16; j++) { WP[j] = 0.0f; WH[j] = 0.0f; }
#pragma unroll
    for (int w = 0; w < 6; w++) {
        float bw = b_in[w];
        bP = fmaf(sgnP[w], bw, bP);
        bH = fmaf(sgnH[w], bw, bH);
#pragma unroll
        for (int j = 0; j < 16; j++) {
            float wv = W_in[w * 16 + j];
            WP[j] = fmaf(sgnP[w], wv, WP[j]);
            WH[j] = fmaf(sgnH[w], wv, WH[j]);
        }
    }

    // ---- per-gate constants, PRE-PERMUTED by lane's gate bits ----
    // slot jg holds constants for gate g = jg ^ lg.
    // dc0P: the (lo,hi) wire-0 pair. dcSP[jg][i]: the pair this lane OWNS for
    // mask m=16>>i (wire w=i+1): lo-slot pair if (lane&m)==0 else hi-slot pair.
    float dc0P[4], dcSP[4][5];
#pragma unroll
    for (int jg = 0; jg < 4; jg++) {
        int g = jg ^ lg;
        const float* wp = (g == 0) ? wf : (g == 1) ? wi : (g == 2) ? wg : wo;
        float cLo = Cphase(wp, kLo);
        float cHi = Cphase(wp, kHi);
        dc0P[jg] = reduce2pi(cHi - cLo);
#pragma unroll
        for (int i = 0; i < 5; i++) {
            int m = 16 >> i;
            int kSel = (lane & m) ? kHi : kLo;
            float cS = (lane & m) ? cHi : cLo;
            dcSP[jg][i] = reduce2pi(Cphase(wp, kSel ^ m) - cS);
        }
    }

    // ---- W_out row: every wire weight 2 (one orientation per pair) ----
    float woutS[6];
#pragma unroll
    for (int w = 0; w < 6; w++)
        woutS[w] = W_out[ch * 6 + w] * (2.0f / 64.0f);
    const float boutv = b_out[ch];

    // ---- branch-free activation: act = aT * tanh(sT*z) + bT ----
    const float sT = (lg == 2) ? 1.0f : 0.5f;
    const float aT = (lg == 2) ? 1.0f : 0.5f;
    const float bT = (lg == 2) ? 0.0f : 0.5f;

    const float4* xrow = (const float4*)(x + (size_t)s * TSTEPS * 8);
    float* orow = out + (size_t)s * TSTEPS * 8;

    float creg = 0.0f, hreg = 0.0f;  // lane owns channel ch (x4 replicated)

    for (int t = 0; t < TSTEPS; t++) {
        // ---- x_t via two float4 broadcast loads; x-chain independent of h ----
        float4 xa = xrow[t * 2];
        float4 xb = xrow[t * 2 + 1];
        float xpl = bP, xph = bH;
        {
            float xs[8] = {xa.x, xa.y, xa.z, xa.w, xb.x, xb.y, xb.z, xb.w};
#pragma unroll
            for (int j = 0; j < 8; j++) {
                xpl = fmaf(WP[8 + j], xs[j], xpl);
                xph = fmaf(WH[8 + j], xs[j], xph);
            }
        }

        // ---- h-chain (recurrence-critical), joined with x-chain ----
        float hpl = 0.0f, hph = 0.0f;
#pragma unroll
        for (int j = 0; j < 8; j++) {
            float hj = shi(hreg, j);
            hpl = fmaf(WP[j], hj, hpl);
            hph = fmaf(WH[j], hj, hph);
        }
        float apl = reduce2pi(xpl + hpl);
        float aph = reduce2pi(xph + hph);

        // ---- one shuffle per wire serves both pair orientations ----
        float Da0 = aph - apl;
        float DaS[5];
#pragma unroll
        for (int i = 0; i < 5; i++) {
            const int m = 16 >> i;
            const bool b = (lane & m) != 0;
            float send = b ? apl : aph;   // partner needs my OPPOSITE slot
            float own  = b ? aph : apl;
            DaS[i] = shx(send, m) - own;
        }

        // ---- per-lane partials, dense gate-permuted slots: q[jg*6 + w] ----
        float q[24];
#pragma unroll
        for (int jg = 0; jg < 4; jg++) {
            q[jg * 6] = __cosf(Da0 + dc0P[jg]);
#pragma unroll
            for (int i = 0; i < 5; i++)
                q[jg * 6 + 1 + i] = __cosf(DaS[i] + dcSP[jg][i]);
        }

        // ---- gate stages: SELECTION-FREE (xor-permuted), dense layout ----
#pragma unroll
        for (int i = 0; i < 12; i++)
            q[i] += shx(q[i + 12], 16);
#pragma unroll
        for (int i = 0; i < 6; i++)
            q[i] += shx(q[i + 6], 8);

        // ---- w-stages (routed): masks 4, 2, 1 over 8 slots (2 zero pads) ----
        float qq[8] = {q[0], q[1], q[2], q[3], q[4], q[5], 0.0f, 0.0f};
#pragma unroll
        for (int half = 4; half >= 1; half >>= 1) {
            const bool up = (lane & half) != 0;
#pragma unroll
            for (int i = 0; i < half; i++) {
                float keep = up ? qq[i + half] : qq[i];
                float send = up ? qq[i] : qq[i + half];
                qq[i] = keep + shx(send, half);
            }
        }
        // lane l holds S for (gate = l>>3, w = l&7); w=6,7 are zero pads.
        const float S = qq[0];

        // ---- z for (gate = l>>3, ch = l&7) via shuffle-matmul ----
        const int base = lane & 24;
        float z = boutv;
#pragma unroll
        for (int w = 0; w < 6; w++) z = fmaf(woutS[w], shi(S, base + w), z);

        // ---- activation FIRST (one MUFU.TANH per lane), then gather ----
        float act = fmaf(aT, tanh_fast(sT * z), bT);
        float fg = shi(act, ch);
        float ig = shi(act, ch + 8);
        float gg = shi(act, ch + 16);
        float og = shi(act, ch + 24);

        // ---- LSTM cell ----
        creg = fmaf(fg, creg, ig * gg);
        hreg = og * tanh_fast(creg);
        if (lane < 8) orow[t * 8 + lane] = hreg;
    }
}

extern "C" void kernel_launch(void* const* d_in, const int* in_sizes, int n_in,
                              void* d_out, int out_size) {
    const float* x     = (const float*)d_in[0];
    const float* W_in  = (const float*)d_in[1];
    const float* b_in  = (const float*)d_in[2];
    const float* W_out = (const float*)d_in[3];
    const float* b_out = (const float*)d_in[4];
    const float* wf    = (const float*)d_in[5];
    const float* wi    = (const float*)d_in[6];
    const float* wg    = (const float*)d_in[7];
    const float* wo    = (const float*)d_in[8];
    float* out = (float*)d_out;

    qlstm_kernel<<<BATCH, 32>>>(x, W_in, b_in, W_out, b_out, wf, wi, wg, wo, out);
}